// round 11
// baseline (speedup 1.0000x reference)
#include <cuda_runtime.h>
#include <cstdint>

#define NUSER 100000
#define NITEM 100000
#define NE    600000
#define NTOT  300000   // concatenated degree entries: [uu | iu | ui]

// ---------------- scratch (device globals; allocation-free) ----------------
__device__ float4 g_Wh_uu[NUSER * 32];   // [NU,128] projected feats
__device__ float4 g_Wh_ui[NUSER * 32];
__device__ float4 g_Wh_iu[NITEM * 32];
__device__ float4 g_acc_uu[NUSER * 32];  // segment sums (layer 0)
__device__ float4 g_acc_iu[NUSER * 32];
__device__ float4 g_acc_ui[NITEM * 32];
__device__ float4 g_Wh1_uu[NUSER * 4];   // [NU,16]
__device__ float4 g_Wh1_iu[NITEM * 4];
__device__ int    g_deg[NTOT];
__device__ int    g_rowstart[NTOT];
__device__ int    g_cursor[NTOT];
__device__ int    g_slot[3 * NE];
__device__ int    g_total;

__device__ __forceinline__ float tf32r(float x) {
    uint32_t u;
    asm("cvt.rna.tf32.f32 %0, %1;" : "=r"(u) : "f"(x));
    return __uint_as_float(u);
}

// ---------------- CSR build ----------------
__global__ void zero_deg() {
    int i = blockIdx.x * blockDim.x + threadIdx.x;
    if (i < NTOT) g_deg[i] = 0;
    if (i == 0) g_total = 0;
}

__global__ void hist_all(const int* __restrict__ d0, const int* __restrict__ d1,
                         const int* __restrict__ d2) {
    int i = blockIdx.x * blockDim.x + threadIdx.x;
    if (i < NE) atomicAdd(&g_deg[d0[i]], 1);
    else if (i < 2 * NE) atomicAdd(&g_deg[100000 + d1[i - NE]], 1);
    else if (i < 3 * NE) atomicAdd(&g_deg[200000 + d2[i - 2 * NE]], 1);
}

// warp-aggregated offsets: one kernel replaces the 3-kernel scan.
// Row ranges are disjoint by construction; placement order is irrelevant
// because every consumer uses [rowstart[i], rowstart[i]+deg[i]).
__global__ void offsets_k() {
    int i = blockIdx.x * blockDim.x + threadIdx.x;
    int lane = threadIdx.x & 31;
    int d = (i < NTOT) ? g_deg[i] : 0;
    int x = d;
#pragma unroll
    for (int o = 1; o < 32; o <<= 1) {
        int y = __shfl_up_sync(0xffffffff, x, o);
        if (lane >= o) x += y;
    }
    int excl = x - d;
    int base = 0;
    if (lane == 31) base = atomicAdd(&g_total, x);
    base = __shfl_sync(0xffffffff, base, 31);
    if (i < NTOT) {
        int ex = base + excl;
        g_rowstart[i] = ex;
        g_cursor[i] = ex;
    }
}

__global__ void fill_all(const int* __restrict__ s0, const int* __restrict__ d0,
                         const int* __restrict__ s1, const int* __restrict__ d1,
                         const int* __restrict__ s2, const int* __restrict__ d2) {
    int i = blockIdx.x * blockDim.x + threadIdx.x;
    int off, sv, dv;
    if (i < NE)            { off = 0;      sv = s0[i];          dv = d0[i]; }
    else if (i < 2 * NE)   { off = 100000; sv = s1[i - NE];     dv = d1[i - NE]; }
    else if (i < 3 * NE)   { off = 200000; sv = s2[i - 2 * NE]; dv = d2[i - 2 * NE]; }
    else return;
    int pos = atomicAdd(&g_cursor[off + dv], 1);
    g_slot[pos] = sv;
}

// ---------------- merged GEMM + reduce launch ----------------
// blocks [0, nGemm): tf32 GEMM Y[gw] = X@W + bias (128x128 tile, BK=16, dbuf)
// blocks [nGemm, ...): CSR gather-reduce of g_Wh[rw] -> g_acc[rw] (warp/node)
// gemm X reads are evict-first (__ldcs); reduce acc writes evict-first (__stcs)
// so the two live Wh tables stay L2-resident.
__global__ __launch_bounds__(256) void merged_gr(
    const float* __restrict__ X, const float* __restrict__ W,
    const float* __restrict__ bias, int M, int gw, int rw, int nGemm) {
    if ((int)blockIdx.x >= nGemm) {
        // ---- reduce path ----
        if (rw < 0) return;
        int idx = blockIdx.x - nGemm;
        int w = idx * 8 + (threadIdx.x >> 5);
        int lane = threadIdx.x & 31;
        if (w >= 100000) return;
        const float4* Wh = (rw == 0) ? g_Wh_uu : (rw == 1) ? g_Wh_iu : g_Wh_ui;
        float4* acc = (rw == 0) ? g_acc_uu : (rw == 1) ? g_acc_iu : g_acc_ui;
        int off = rw * 100000;
        int beg = g_rowstart[off + w];
        int end = beg + g_deg[off + w];
        float4 s = make_float4(0.f, 0.f, 0.f, 0.f);
        for (int j = beg; j < end; j++) {
            int sc = g_slot[j];
            float4 v = __ldg(&Wh[(size_t)sc * 32 + lane]);
            s.x += v.x; s.y += v.y; s.z += v.z; s.w += v.w;
        }
        __stcs(&acc[(size_t)w * 32 + lane], s);
        return;
    }
    // ---- gemm path (R5 tf32, double-buffered) ----
    float* Y = (gw == 0) ? (float*)g_Wh_uu
             : (gw == 1) ? (float*)g_Wh_ui
                         : (float*)g_Wh_iu;
    __shared__ __align__(16) float Am[2][128][20];
    __shared__ __align__(16) float Bs[2][16][136];
    const int tid = threadIdx.x;
    const int lane = tid & 31;
    const int wid = tid >> 5;
    const int warp_m = wid & 3;
    const int warp_n = wid >> 2;
    const int bm = blockIdx.x * 128;
    const int g = lane >> 2;
    const int t = lane & 3;

    const int fA0 = tid, fA1 = tid + 256;
    const int mA0 = fA0 >> 2, kqA0 = fA0 & 3;
    const int mA1 = fA1 >> 2, kqA1 = fA1 & 3;
    const int kB0 = fA0 >> 5, nB0 = (fA0 & 31) * 4;
    const int kB1 = fA1 >> 5, nB1 = (fA1 & 31) * 4;
    const int rowA0 = bm + mA0, rowA1 = bm + mA1;

    float c[2][8][4];
#pragma unroll
    for (int mt = 0; mt < 2; mt++)
#pragma unroll
        for (int nt = 0; nt < 8; nt++)
#pragma unroll
            for (int q = 0; q < 4; q++) c[mt][nt][q] = 0.f;

    float4 ra0, ra1, rb0, rb1;

#define LOAD_REGS(K0)                                                              \
    {                                                                              \
        ra0 = make_float4(0.f, 0.f, 0.f, 0.f);                                     \
        ra1 = make_float4(0.f, 0.f, 0.f, 0.f);                                     \
        if (rowA0 < M) ra0 = __ldcs((const float4*)(X + (size_t)rowA0 * 128 + (K0) + kqA0 * 4)); \
        if (rowA1 < M) ra1 = __ldcs((const float4*)(X + (size_t)rowA1 * 128 + (K0) + kqA1 * 4)); \
        rb0 = *(const float4*)(W + (size_t)((K0) + kB0) * 128 + nB0);              \
        rb1 = *(const float4*)(W + (size_t)((K0) + kB1) * 128 + nB1);              \
    }

#define STORE_BUF(B)                                                               \
    {                                                                              \
        float4 u;                                                                  \
        u.x = tf32r(ra0.x); u.y = tf32r(ra0.y); u.z = tf32r(ra0.z); u.w = tf32r(ra0.w); \
        *(float4*)&Am[B][mA0][kqA0 * 4] = u;                                       \
        u.x = tf32r(ra1.x); u.y = tf32r(ra1.y); u.z = tf32r(ra1.z); u.w = tf32r(ra1.w); \
        *(float4*)&Am[B][mA1][kqA1 * 4] = u;                                       \
        u.x = tf32r(rb0.x); u.y = tf32r(rb0.y); u.z = tf32r(rb0.z); u.w = tf32r(rb0.w); \
        *(float4*)&Bs[B][kB0][nB0] = u;                                            \
        u.x = tf32r(rb1.x); u.y = tf32r(rb1.y); u.z = tf32r(rb1.z); u.w = tf32r(rb1.w); \
        *(float4*)&Bs[B][kB1][nB1] = u;                                            \
    }

    LOAD_REGS(0);
    STORE_BUF(0);
    __syncthreads();

    int cur = 0;
#pragma unroll
    for (int it = 0; it < 8; it++) {
        if (it < 7) LOAD_REGS((it + 1) * 16);
#pragma unroll
        for (int kk = 0; kk < 16; kk += 8) {
            uint32_t a[2][4], b[8][2];
#pragma unroll
            for (int mt = 0; mt < 2; mt++) {
                int r = warp_m * 32 + mt * 16 + g;
                a[mt][0] = __float_as_uint(Am[cur][r][kk + t]);
                a[mt][1] = __float_as_uint(Am[cur][r + 8][kk + t]);
                a[mt][2] = __float_as_uint(Am[cur][r][kk + t + 4]);
                a[mt][3] = __float_as_uint(Am[cur][r + 8][kk + t + 4]);
            }
#pragma unroll
            for (int nt = 0; nt < 8; nt++) {
                int cn = warp_n * 64 + nt * 8 + g;
                b[nt][0] = __float_as_uint(Bs[cur][kk + t][cn]);
                b[nt][1] = __float_as_uint(Bs[cur][kk + t + 4][cn]);
            }
#pragma unroll
            for (int mt = 0; mt < 2; mt++)
#pragma unroll
                for (int nt = 0; nt < 8; nt++) {
                    asm volatile(
                        "mma.sync.aligned.m16n8k8.row.col.f32.tf32.tf32.f32 "
                        "{%0,%1,%2,%3},{%4,%5,%6,%7},{%8,%9},{%0,%1,%2,%3};"
                        : "+f"(c[mt][nt][0]), "+f"(c[mt][nt][1]),
                          "+f"(c[mt][nt][2]), "+f"(c[mt][nt][3])
                        : "r"(a[mt][0]), "r"(a[mt][1]), "r"(a[mt][2]), "r"(a[mt][3]),
                          "r"(b[nt][0]), "r"(b[nt][1]));
                }
        }
        if (it < 7) {
            STORE_BUF(cur ^ 1);
            __syncthreads();
            cur ^= 1;
        }
    }
#undef LOAD_REGS
#undef STORE_BUF

#pragma unroll
    for (int nt = 0; nt < 8; nt++) {
        int col = warp_n * 64 + nt * 8 + t * 2;
        float2 bb = *(const float2*)(bias + col);
#pragma unroll
        for (int mt = 0; mt < 2; mt++) {
            int r0 = bm + warp_m * 32 + mt * 16 + g;
            if (r0 < M) {
                float2 o = make_float2(c[mt][nt][0] + bb.x, c[mt][nt][1] + bb.y);
                *(float2*)(Y + (size_t)r0 * 128 + col) = o;
            }
            int r1 = r0 + 8;
            if (r1 < M) {
                float2 o = make_float2(c[mt][nt][2] + bb.x, c[mt][nt][3] + bb.y);
                *(float2*)(Y + (size_t)r1 * 128 + col) = o;
            }
        }
    }
}

// ---------------- skinny GEMM (both ntypes, one launch) ---------------------
// user blocks [0,1563): h_user = relu(acc_uu/deg + acc_iu/deg) @ W1_uu + b1_uu
// item blocks [1563, 3126): h_item = relu(acc_ui/deg) @ W1_iu + b1_iu
__global__ __launch_bounds__(256) void gemm16_both(
    const float* __restrict__ Wu, const float* __restrict__ bu,
    const float* __restrict__ Wi, const float* __restrict__ bi) {
    const bool item = blockIdx.x >= 1563;
    const float* W = item ? Wi : Wu;
    const float* b = item ? bi : bu;
    float* Y = item ? (float*)g_Wh1_iu : (float*)g_Wh1_uu;
    const int M = item ? NITEM : NUSER;
    const int base = (item ? blockIdx.x - 1563 : blockIdx.x) * 64;

    __shared__ float Xs[64][130];
    __shared__ float Ws[128 * 16];
    __shared__ float bs[16];
    int tid = threadIdx.x;
#pragma unroll
    for (int i = 0; i < 8; i++) Ws[tid + i * 256] = W[tid + i * 256];
    if (tid < 16) bs[tid] = b[tid];
#pragma unroll
    for (int i = 0; i < 8; i++) {
        int f = tid + i * 256;
        int r = f >> 5, c4 = f & 31;
        int row = base + r;
        float4 v = make_float4(0.f, 0.f, 0.f, 0.f);
        if (row < M) {
            if (!item) {
                float iu = 1.f / fmaxf((float)g_deg[row], 1.f);
                float ii = 1.f / fmaxf((float)g_deg[100000 + row], 1.f);
                float4 a = g_acc_uu[(size_t)row * 32 + c4];
                float4 c = g_acc_iu[(size_t)row * 32 + c4];
                v.x = fmaxf(a.x * iu + c.x * ii, 0.f);
                v.y = fmaxf(a.y * iu + c.y * ii, 0.f);
                v.z = fmaxf(a.z * iu + c.z * ii, 0.f);
                v.w = fmaxf(a.w * iu + c.w * ii, 0.f);
            } else {
                float inv = 1.f / fmaxf((float)g_deg[200000 + row], 1.f);
                float4 a = g_acc_ui[(size_t)row * 32 + c4];
                v.x = fmaxf(a.x * inv, 0.f);
                v.y = fmaxf(a.y * inv, 0.f);
                v.z = fmaxf(a.z * inv, 0.f);
                v.w = fmaxf(a.w * inv, 0.f);
            }
        }
        Xs[r][c4 * 4 + 0] = v.x; Xs[r][c4 * 4 + 1] = v.y;
        Xs[r][c4 * 4 + 2] = v.z; Xs[r][c4 * 4 + 3] = v.w;
    }
    __syncthreads();
    int r = tid >> 2, cb = (tid & 3) * 4;
    float4 acc = make_float4(0.f, 0.f, 0.f, 0.f);
#pragma unroll 8
    for (int k = 0; k < 128; k++) {
        float x = Xs[r][k];
        float4 w = *(float4*)&Ws[k * 16 + cb];
        acc.x = fmaf(x, w.x, acc.x);
        acc.y = fmaf(x, w.y, acc.y);
        acc.z = fmaf(x, w.z, acc.z);
        acc.w = fmaf(x, w.w, acc.w);
    }
    int row = base + r;
    if (row < M) {
        float4 o;
        o.x = acc.x + bs[cb + 0];
        o.y = acc.y + bs[cb + 1];
        o.z = acc.z + bs[cb + 2];
        o.w = acc.w + bs[cb + 3];
        *(float4*)(Y + (size_t)row * 16 + cb) = o;
    }
}

// ---------------- layer-1 reduce (both etypes) + mean combine -> d_out ------
__global__ void reduce16_final(float4* __restrict__ out) {
    int id = blockIdx.x * blockDim.x + threadIdx.x;
    int n = id >> 2, part = id & 3;
    if (n >= NUSER) return;
    float4 s0 = make_float4(0.f, 0.f, 0.f, 0.f);
    {
        int beg = g_rowstart[n], end = beg + g_deg[n];
        for (int j = beg; j < end; j++) {
            int sc = g_slot[j];
            float4 v = __ldg(&g_Wh1_uu[(size_t)sc * 4 + part]);
            s0.x += v.x; s0.y += v.y; s0.z += v.z; s0.w += v.w;
        }
    }
    float4 s1 = make_float4(0.f, 0.f, 0.f, 0.f);
    {
        int beg = g_rowstart[100000 + n], end = beg + g_deg[100000 + n];
        for (int j = beg; j < end; j++) {
            int sc = g_slot[j];
            float4 v = __ldg(&g_Wh1_iu[(size_t)sc * 4 + part]);
            s1.x += v.x; s1.y += v.y; s1.z += v.z; s1.w += v.w;
        }
    }
    float iu = 1.f / fmaxf((float)g_deg[n], 1.f);
    float ii = 1.f / fmaxf((float)g_deg[100000 + n], 1.f);
    float4 o;
    o.x = s0.x * iu + s1.x * ii;
    o.y = s0.y * iu + s1.y * ii;
    o.z = s0.z * iu + s1.z * ii;
    o.w = s0.w * iu + s1.w * ii;
    out[(size_t)n * 4 + part] = o;
}

// ---------------- launch ----------------
extern "C" void kernel_launch(void* const* d_in, const int* in_sizes, int n_in,
                              void* d_out, int out_size) {
    const float* embed_user = (const float*)d_in[0];
    const float* embed_item = (const float*)d_in[1];
    const int* src_uu = (const int*)d_in[2];
    const int* dst_uu = (const int*)d_in[3];
    const int* src_ui = (const int*)d_in[4];
    const int* dst_ui = (const int*)d_in[5];
    const int* src_iu = (const int*)d_in[6];
    const int* dst_iu = (const int*)d_in[7];
    const float* W0_uu = (const float*)d_in[8];
    const float* b0_uu = (const float*)d_in[9];
    const float* W0_ui = (const float*)d_in[10];
    const float* b0_ui = (const float*)d_in[11];
    const float* W0_iu = (const float*)d_in[12];
    const float* b0_iu = (const float*)d_in[13];
    const float* W1_uu = (const float*)d_in[14];
    const float* b1_uu = (const float*)d_in[15];
    const float* W1_iu = (const float*)d_in[18];
    const float* b1_iu = (const float*)d_in[19];

    const int e3blk = (3 * NE + 255) / 256;
    const int GB = (NUSER + 127) / 128;   // 782 gemm blocks
    const int RB = 100000 / 8;            // 12500 reduce blocks

    // ---- CSR build ----
    zero_deg<<<(NTOT + 255) / 256, 256>>>();
    hist_all<<<e3blk, 256>>>(dst_uu, dst_iu, dst_ui);
    offsets_k<<<(NTOT + 255) / 256, 256>>>();
    fill_all<<<e3blk, 256>>>(src_uu, dst_uu, src_iu, dst_iu, src_ui, dst_ui);

    // ---- layer-0 pipeline: gemm(k+1) overlapped with reduce(k) ----
    merged_gr<<<GB, 256>>>(embed_user, W0_uu, b0_uu, NUSER, 0, -1, GB);       // gemm uu
    merged_gr<<<GB + RB, 256>>>(embed_item, W0_iu, b0_iu, NITEM, 2, 0, GB);   // gemm iu ∥ red uu
    merged_gr<<<GB + RB, 256>>>(embed_user, W0_ui, b0_ui, NUSER, 1, 1, GB);   // gemm ui ∥ red iu
    merged_gr<<<RB, 256>>>(nullptr, nullptr, nullptr, 0, 0, 2, 0);            // red ui

    // ---- layer 1: skinny GEMM (both ntypes, mean+relu fused) ----
    gemm16_both<<<2 * 1563, 256>>>(W1_uu, b1_uu, W1_iu, b1_iu);

    // ---- layer-1 aggregation + mean combine -> output ----
    reduce16_final<<<(NUSER * 4 + 255) / 256, 256>>>((float4*)d_out);
}

// round 12
// speedup vs baseline: 2.4099x; 2.4099x over previous
#include <cuda_runtime.h>
#include <cstdint>

#define NUSER 100000
#define NITEM 100000
#define NE    600000
#define NTOT  300000   // concatenated degree entries: [uu | iu | ui]

// ---------------- scratch (device globals; allocation-free) ----------------
__device__ float4 g_Wh_uu[NUSER * 32];   // [NU,128] projected feats
__device__ float4 g_Wh_ui[NUSER * 32];
__device__ float4 g_Wh_iu[NITEM * 32];
__device__ float4 g_acc_uu[NUSER * 32];  // segment sums (layer 0)
__device__ float4 g_acc_iu[NUSER * 32];
__device__ float4 g_acc_ui[NITEM * 32];
__device__ float4 g_Wh1_uu[NUSER * 4];   // [NU,16]
__device__ float4 g_Wh1_iu[NITEM * 4];
__device__ int    g_deg[NTOT];
__device__ int    g_rowstart[NTOT];
__device__ int    g_cursor[NTOT];
__device__ int    g_slot[3 * NE];
__device__ int    g_total;

__device__ __forceinline__ float tf32r(float x) {
    uint32_t u;
    asm("cvt.rna.tf32.f32 %0, %1;" : "=r"(u) : "f"(x));
    return __uint_as_float(u);
}

// ---------------- CSR build ----------------
__global__ void zero_deg() {
    int i = blockIdx.x * blockDim.x + threadIdx.x;
    if (i < NTOT) g_deg[i] = 0;
    if (i == 0) g_total = 0;
}

__global__ void hist_all(const int* __restrict__ d0, const int* __restrict__ d1,
                         const int* __restrict__ d2) {
    int i = blockIdx.x * blockDim.x + threadIdx.x;
    if (i < NE) atomicAdd(&g_deg[d0[i]], 1);
    else if (i < 2 * NE) atomicAdd(&g_deg[100000 + d1[i - NE]], 1);
    else if (i < 3 * NE) atomicAdd(&g_deg[200000 + d2[i - 2 * NE]], 1);
}

// warp-aggregated offsets: replaces the 3-kernel scan. Row ranges are
// disjoint; placement order is irrelevant since consumers use beg+deg.
__global__ void offsets_k() {
    int i = blockIdx.x * blockDim.x + threadIdx.x;
    int lane = threadIdx.x & 31;
    int d = (i < NTOT) ? g_deg[i] : 0;
    int x = d;
#pragma unroll
    for (int o = 1; o < 32; o <<= 1) {
        int y = __shfl_up_sync(0xffffffff, x, o);
        if (lane >= o) x += y;
    }
    int excl = x - d;
    int base = 0;
    if (lane == 31) base = atomicAdd(&g_total, x);
    base = __shfl_sync(0xffffffff, base, 31);
    if (i < NTOT) {
        int ex = base + excl;
        g_rowstart[i] = ex;
        g_cursor[i] = ex;
    }
}

__global__ void fill_all(const int* __restrict__ s0, const int* __restrict__ d0,
                         const int* __restrict__ s1, const int* __restrict__ d1,
                         const int* __restrict__ s2, const int* __restrict__ d2) {
    int i = blockIdx.x * blockDim.x + threadIdx.x;
    int off, sv, dv;
    if (i < NE)            { off = 0;      sv = s0[i];          dv = d0[i]; }
    else if (i < 2 * NE)   { off = 100000; sv = s1[i - NE];     dv = d1[i - NE]; }
    else if (i < 3 * NE)   { off = 200000; sv = s2[i - 2 * NE]; dv = d2[i - 2 * NE]; }
    else return;
    int pos = atomicAdd(&g_cursor[off + dv], 1);
    g_slot[pos] = sv;
}

// ---------------- TF32 tensor-core GEMM (R5-identical) ----------------------
// Y[M,128] = X[M,128] @ W[128,128] + b; 128x128 tile, BK=16, dbuf smem.
__global__ __launch_bounds__(256) void gemm128(
    const float* __restrict__ X, const float* __restrict__ W,
    const float* __restrict__ bias, int M, int which) {
    float* Y = (which == 0) ? (float*)g_Wh_uu
             : (which == 1) ? (float*)g_Wh_ui
                            : (float*)g_Wh_iu;
    __shared__ __align__(16) float Am[2][128][20];
    __shared__ __align__(16) float Bs[2][16][136];
    const int tid = threadIdx.x;
    const int lane = tid & 31;
    const int wid = tid >> 5;
    const int warp_m = wid & 3;
    const int warp_n = wid >> 2;
    const int bm = blockIdx.x * 128;
    const int g = lane >> 2;
    const int t = lane & 3;

    const int fA0 = tid, fA1 = tid + 256;
    const int mA0 = fA0 >> 2, kqA0 = fA0 & 3;
    const int mA1 = fA1 >> 2, kqA1 = fA1 & 3;
    const int kB0 = fA0 >> 5, nB0 = (fA0 & 31) * 4;
    const int kB1 = fA1 >> 5, nB1 = (fA1 & 31) * 4;
    const int rowA0 = bm + mA0, rowA1 = bm + mA1;

    float c[2][8][4];
#pragma unroll
    for (int mt = 0; mt < 2; mt++)
#pragma unroll
        for (int nt = 0; nt < 8; nt++)
#pragma unroll
            for (int q = 0; q < 4; q++) c[mt][nt][q] = 0.f;

    float4 ra0, ra1, rb0, rb1;

#define LOAD_REGS(K0)                                                              \
    {                                                                              \
        ra0 = make_float4(0.f, 0.f, 0.f, 0.f);                                     \
        ra1 = make_float4(0.f, 0.f, 0.f, 0.f);                                     \
        if (rowA0 < M) ra0 = *(const float4*)(X + (size_t)rowA0 * 128 + (K0) + kqA0 * 4); \
        if (rowA1 < M) ra1 = *(const float4*)(X + (size_t)rowA1 * 128 + (K0) + kqA1 * 4); \
        rb0 = *(const float4*)(W + (size_t)((K0) + kB0) * 128 + nB0);              \
        rb1 = *(const float4*)(W + (size_t)((K0) + kB1) * 128 + nB1);              \
    }

#define STORE_BUF(B)                                                               \
    {                                                                              \
        float4 u;                                                                  \
        u.x = tf32r(ra0.x); u.y = tf32r(ra0.y); u.z = tf32r(ra0.z); u.w = tf32r(ra0.w); \
        *(float4*)&Am[B][mA0][kqA0 * 4] = u;                                       \
        u.x = tf32r(ra1.x); u.y = tf32r(ra1.y); u.z = tf32r(ra1.z); u.w = tf32r(ra1.w); \
        *(float4*)&Am[B][mA1][kqA1 * 4] = u;                                       \
        u.x = tf32r(rb0.x); u.y = tf32r(rb0.y); u.z = tf32r(rb0.z); u.w = tf32r(rb0.w); \
        *(float4*)&Bs[B][kB0][nB0] = u;                                            \
        u.x = tf32r(rb1.x); u.y = tf32r(rb1.y); u.z = tf32r(rb1.z); u.w = tf32r(rb1.w); \
        *(float4*)&Bs[B][kB1][nB1] = u;                                            \
    }

    LOAD_REGS(0);
    STORE_BUF(0);
    __syncthreads();

    int cur = 0;
#pragma unroll
    for (int it = 0; it < 8; it++) {
        if (it < 7) LOAD_REGS((it + 1) * 16);
#pragma unroll
        for (int kk = 0; kk < 16; kk += 8) {
            uint32_t a[2][4], b[8][2];
#pragma unroll
            for (int mt = 0; mt < 2; mt++) {
                int r = warp_m * 32 + mt * 16 + g;
                a[mt][0] = __float_as_uint(Am[cur][r][kk + t]);
                a[mt][1] = __float_as_uint(Am[cur][r + 8][kk + t]);
                a[mt][2] = __float_as_uint(Am[cur][r][kk + t + 4]);
                a[mt][3] = __float_as_uint(Am[cur][r + 8][kk + t + 4]);
            }
#pragma unroll
            for (int nt = 0; nt < 8; nt++) {
                int cn = warp_n * 64 + nt * 8 + g;
                b[nt][0] = __float_as_uint(Bs[cur][kk + t][cn]);
                b[nt][1] = __float_as_uint(Bs[cur][kk + t + 4][cn]);
            }
#pragma unroll
            for (int mt = 0; mt < 2; mt++)
#pragma unroll
                for (int nt = 0; nt < 8; nt++) {
                    asm volatile(
                        "mma.sync.aligned.m16n8k8.row.col.f32.tf32.tf32.f32 "
                        "{%0,%1,%2,%3},{%4,%5,%6,%7},{%8,%9},{%0,%1,%2,%3};"
                        : "+f"(c[mt][nt][0]), "+f"(c[mt][nt][1]),
                          "+f"(c[mt][nt][2]), "+f"(c[mt][nt][3])
                        : "r"(a[mt][0]), "r"(a[mt][1]), "r"(a[mt][2]), "r"(a[mt][3]),
                          "r"(b[nt][0]), "r"(b[nt][1]));
                }
        }
        if (it < 7) {
            STORE_BUF(cur ^ 1);
            __syncthreads();
            cur ^= 1;
        }
    }
#undef LOAD_REGS
#undef STORE_BUF

#pragma unroll
    for (int nt = 0; nt < 8; nt++) {
        int col = warp_n * 64 + nt * 8 + t * 2;
        float2 bb = *(const float2*)(bias + col);
#pragma unroll
        for (int mt = 0; mt < 2; mt++) {
            int r0 = bm + warp_m * 32 + mt * 16 + g;
            if (r0 < M) {
                float2 o = make_float2(c[mt][nt][0] + bb.x, c[mt][nt][1] + bb.y);
                *(float2*)(Y + (size_t)r0 * 128 + col) = o;
            }
            int r1 = r0 + 8;
            if (r1 < M) {
                float2 o = make_float2(c[mt][nt][2] + bb.x, c[mt][nt][3] + bb.y);
                *(float2*)(Y + (size_t)r1 * 128 + col) = o;
            }
        }
    }
}

// ---------------- CSR gather-reduce, 128-wide (R5-identical, beg+deg) -------
__global__ void reduce128(int which) {
    const float4* Wh = (which == 0) ? g_Wh_uu : (which == 1) ? g_Wh_iu : g_Wh_ui;
    float4* acc = (which == 0) ? g_acc_uu : (which == 1) ? g_acc_iu : g_acc_ui;
    int w = (blockIdx.x * blockDim.x + threadIdx.x) >> 5;
    int lane = threadIdx.x & 31;
    if (w >= 100000) return;
    int off = which * 100000;
    int beg = g_rowstart[off + w];
    int end = beg + g_deg[off + w];
    float4 s = make_float4(0.f, 0.f, 0.f, 0.f);
    for (int j = beg; j < end; j++) {
        int sc = g_slot[j];
        float4 v = Wh[(size_t)sc * 32 + lane];
        s.x += v.x; s.y += v.y; s.z += v.z; s.w += v.w;
    }
    acc[(size_t)w * 32 + lane] = s;
}

// ---------------- skinny GEMM (both ntypes, one launch; mean+relu fused) ----
__global__ __launch_bounds__(256) void gemm16_both(
    const float* __restrict__ Wu, const float* __restrict__ bu,
    const float* __restrict__ Wi, const float* __restrict__ bi) {
    const bool item = blockIdx.x >= 1563;
    const float* W = item ? Wi : Wu;
    const float* b = item ? bi : bu;
    float* Y = item ? (float*)g_Wh1_iu : (float*)g_Wh1_uu;
    const int M = item ? NITEM : NUSER;
    const int base = (item ? blockIdx.x - 1563 : blockIdx.x) * 64;

    __shared__ float Xs[64][130];
    __shared__ float Ws[128 * 16];
    __shared__ float bs[16];
    int tid = threadIdx.x;
#pragma unroll
    for (int i = 0; i < 8; i++) Ws[tid + i * 256] = W[tid + i * 256];
    if (tid < 16) bs[tid] = b[tid];
#pragma unroll
    for (int i = 0; i < 8; i++) {
        int f = tid + i * 256;
        int r = f >> 5, c4 = f & 31;
        int row = base + r;
        float4 v = make_float4(0.f, 0.f, 0.f, 0.f);
        if (row < M) {
            if (!item) {
                float iu = 1.f / fmaxf((float)g_deg[row], 1.f);
                float ii = 1.f / fmaxf((float)g_deg[100000 + row], 1.f);
                float4 a = g_acc_uu[(size_t)row * 32 + c4];
                float4 c = g_acc_iu[(size_t)row * 32 + c4];
                v.x = fmaxf(a.x * iu + c.x * ii, 0.f);
                v.y = fmaxf(a.y * iu + c.y * ii, 0.f);
                v.z = fmaxf(a.z * iu + c.z * ii, 0.f);
                v.w = fmaxf(a.w * iu + c.w * ii, 0.f);
            } else {
                float inv = 1.f / fmaxf((float)g_deg[200000 + row], 1.f);
                float4 a = g_acc_ui[(size_t)row * 32 + c4];
                v.x = fmaxf(a.x * inv, 0.f);
                v.y = fmaxf(a.y * inv, 0.f);
                v.z = fmaxf(a.z * inv, 0.f);
                v.w = fmaxf(a.w * inv, 0.f);
            }
        }
        Xs[r][c4 * 4 + 0] = v.x; Xs[r][c4 * 4 + 1] = v.y;
        Xs[r][c4 * 4 + 2] = v.z; Xs[r][c4 * 4 + 3] = v.w;
    }
    __syncthreads();
    int r = tid >> 2, cb = (tid & 3) * 4;
    float4 acc = make_float4(0.f, 0.f, 0.f, 0.f);
#pragma unroll 8
    for (int k = 0; k < 128; k++) {
        float x = Xs[r][k];
        float4 w = *(float4*)&Ws[k * 16 + cb];
        acc.x = fmaf(x, w.x, acc.x);
        acc.y = fmaf(x, w.y, acc.y);
        acc.z = fmaf(x, w.z, acc.z);
        acc.w = fmaf(x, w.w, acc.w);
    }
    int row = base + r;
    if (row < M) {
        float4 o;
        o.x = acc.x + bs[cb + 0];
        o.y = acc.y + bs[cb + 1];
        o.z = acc.z + bs[cb + 2];
        o.w = acc.w + bs[cb + 3];
        *(float4*)(Y + (size_t)row * 16 + cb) = o;
    }
}

// ---------------- layer-1 reduce (both etypes) + mean combine -> d_out ------
__global__ void reduce16_final(float4* __restrict__ out) {
    int id = blockIdx.x * blockDim.x + threadIdx.x;
    int n = id >> 2, part = id & 3;
    if (n >= NUSER) return;
    float4 s0 = make_float4(0.f, 0.f, 0.f, 0.f);
    {
        int beg = g_rowstart[n], end = beg + g_deg[n];
        for (int j = beg; j < end; j++) {
            int sc = g_slot[j];
            float4 v = __ldg(&g_Wh1_uu[(size_t)sc * 4 + part]);
            s0.x += v.x; s0.y += v.y; s0.z += v.z; s0.w += v.w;
        }
    }
    float4 s1 = make_float4(0.f, 0.f, 0.f, 0.f);
    {
        int beg = g_rowstart[100000 + n], end = beg + g_deg[100000 + n];
        for (int j = beg; j < end; j++) {
            int sc = g_slot[j];
            float4 v = __ldg(&g_Wh1_iu[(size_t)sc * 4 + part]);
            s1.x += v.x; s1.y += v.y; s1.z += v.z; s1.w += v.w;
        }
    }
    float iu = 1.f / fmaxf((float)g_deg[n], 1.f);
    float ii = 1.f / fmaxf((float)g_deg[100000 + n], 1.f);
    float4 o;
    o.x = s0.x * iu + s1.x * ii;
    o.y = s0.y * iu + s1.y * ii;
    o.z = s0.z * iu + s1.z * ii;
    o.w = s0.w * iu + s1.w * ii;
    out[(size_t)n * 4 + part] = o;
}

// ---------------- launch ----------------
extern "C" void kernel_launch(void* const* d_in, const int* in_sizes, int n_in,
                              void* d_out, int out_size) {
    const float* embed_user = (const float*)d_in[0];
    const float* embed_item = (const float*)d_in[1];
    const int* src_uu = (const int*)d_in[2];
    const int* dst_uu = (const int*)d_in[3];
    const int* src_ui = (const int*)d_in[4];
    const int* dst_ui = (const int*)d_in[5];
    const int* src_iu = (const int*)d_in[6];
    const int* dst_iu = (const int*)d_in[7];
    const float* W0_uu = (const float*)d_in[8];
    const float* b0_uu = (const float*)d_in[9];
    const float* W0_ui = (const float*)d_in[10];
    const float* b0_ui = (const float*)d_in[11];
    const float* W0_iu = (const float*)d_in[12];
    const float* b0_iu = (const float*)d_in[13];
    const float* W1_uu = (const float*)d_in[14];
    const float* b1_uu = (const float*)d_in[15];
    const float* W1_iu = (const float*)d_in[18];
    const float* b1_iu = (const float*)d_in[19];

    const int e3blk = (3 * NE + 255) / 256;
    const int rblk = (100000 * 32 + 255) / 256;

    // ---- CSR build (4 launches) ----
    zero_deg<<<(NTOT + 255) / 256, 256>>>();
    hist_all<<<e3blk, 256>>>(dst_uu, dst_iu, dst_ui);
    offsets_k<<<(NTOT + 255) / 256, 256>>>();
    fill_all<<<e3blk, 256>>>(src_uu, dst_uu, src_iu, dst_iu, src_ui, dst_ui);

    // ---- layer 0: project (tf32 mma) then reduce while Wh is L2-hot ----
    gemm128<<<(NUSER + 127) / 128, 256>>>(embed_user, W0_uu, b0_uu, NUSER, 0);
    reduce128<<<rblk, 256>>>(0);
    gemm128<<<(NITEM + 127) / 128, 256>>>(embed_item, W0_iu, b0_iu, NITEM, 2);
    reduce128<<<rblk, 256>>>(1);
    gemm128<<<(NUSER + 127) / 128, 256>>>(embed_user, W0_ui, b0_ui, NUSER, 1);
    reduce128<<<rblk, 256>>>(2);

    // ---- layer 1: skinny GEMM (both ntypes), reduce + combine -> out ----
    gemm16_both<<<2 * 1563, 256>>>(W1_uu, b1_uu, W1_iu, b1_iu);
    reduce16_final<<<(NUSER * 4 + 255) / 256, 256>>>((float4*)d_out);
}

// round 15
// speedup vs baseline: 2.6838x; 1.1137x over previous
#include <cuda_runtime.h>
#include <cuda_fp16.h>
#include <cstdint>

#define NUSER 100000
#define NITEM 100000
#define NE    600000
#define NTOT  300000   // concatenated degree entries: [uu | iu | ui]

// ---------------- scratch (device globals; allocation-free) ----------------
__device__ __half  g_Wh_uu[NUSER * 128];  // [NU,128] projected feats (fp16)
__device__ __half  g_Wh_ui[NUSER * 128];
__device__ __half  g_Wh_iu[NITEM * 128];
__device__ float4  g_acc_uu[NUSER * 32];  // segment sums (fp32)
__device__ float4  g_acc_iu[NUSER * 32];
__device__ float4  g_acc_ui[NITEM * 32];
__device__ float4  g_Wh1_uu[NUSER * 4];   // [NU,16]
__device__ float4  g_Wh1_iu[NITEM * 4];
__device__ int     g_deg[NTOT];
__device__ int     g_rowstart[NTOT];
__device__ int     g_cursor[NTOT];
__device__ int     g_slot[3 * NE];
__device__ int     g_total;

__device__ __forceinline__ float tf32r(float x) {
    uint32_t u;
    asm("cvt.rna.tf32.f32 %0, %1;" : "=r"(u) : "f"(x));
    return __uint_as_float(u);
}

// ---------------- CSR build ----------------
__global__ void zero_deg() {
    int i = blockIdx.x * blockDim.x + threadIdx.x;
    if (i < NTOT) g_deg[i] = 0;
    if (i == 0) g_total = 0;
}

__global__ void hist_all(const int* __restrict__ d0, const int* __restrict__ d1,
                         const int* __restrict__ d2) {
    int i = blockIdx.x * blockDim.x + threadIdx.x;
    if (i < NE) atomicAdd(&g_deg[d0[i]], 1);
    else if (i < 2 * NE) atomicAdd(&g_deg[100000 + d1[i - NE]], 1);
    else if (i < 3 * NE) atomicAdd(&g_deg[200000 + d2[i - 2 * NE]], 1);
}

// warp-aggregated offsets: replaces the 3-kernel scan. Row ranges are
// disjoint; placement order is irrelevant since consumers use beg+deg.
__global__ void offsets_k() {
    int i = blockIdx.x * blockDim.x + threadIdx.x;
    int lane = threadIdx.x & 31;
    int d = (i < NTOT) ? g_deg[i] : 0;
    int x = d;
#pragma unroll
    for (int o = 1; o < 32; o <<= 1) {
        int y = __shfl_up_sync(0xffffffff, x, o);
        if (lane >= o) x += y;
    }
    int excl = x - d;
    int base = 0;
    if (lane == 31) base = atomicAdd(&g_total, x);
    base = __shfl_sync(0xffffffff, base, 31);
    if (i < NTOT) {
        int ex = base + excl;
        g_rowstart[i] = ex;
        g_cursor[i] = ex;
    }
}

__global__ void fill_all(const int* __restrict__ s0, const int* __restrict__ d0,
                         const int* __restrict__ s1, const int* __restrict__ d1,
                         const int* __restrict__ s2, const int* __restrict__ d2) {
    int i = blockIdx.x * blockDim.x + threadIdx.x;
    int off, sv, dv;
    if (i < NE)            { off = 0;      sv = s0[i];          dv = d0[i]; }
    else if (i < 2 * NE)   { off = 100000; sv = s1[i - NE];     dv = d1[i - NE]; }
    else if (i < 3 * NE)   { off = 200000; sv = s2[i - 2 * NE]; dv = d2[i - 2 * NE]; }
    else return;
    int pos = atomicAdd(&g_cursor[off + dv], 1);
    g_slot[pos] = sv;
}

// ---------------- TF32 tensor-core GEMM, fp16 output --------------------
// Y[M,128] = X[M,128] @ W[128,128] + b; 128x128 tile, BK=16, dbuf smem.
__global__ __launch_bounds__(256) void gemm128(
    const float* __restrict__ X, const float* __restrict__ W,
    const float* __restrict__ bias, int M, int which) {
    __half* Y = (which == 0) ? g_Wh_uu
              : (which == 1) ? g_Wh_ui
                             : g_Wh_iu;
    __shared__ __align__(16) float Am[2][128][20];
    __shared__ __align__(16) float Bs[2][16][136];
    const int tid = threadIdx.x;
    const int lane = tid & 31;
    const int wid = tid >> 5;
    const int warp_m = wid & 3;
    const int warp_n = wid >> 2;
    const int bm = blockIdx.x * 128;
    const int g = lane >> 2;
    const int t = lane & 3;

    const int fA0 = tid, fA1 = tid + 256;
    const int mA0 = fA0 >> 2, kqA0 = fA0 & 3;
    const int mA1 = fA1 >> 2, kqA1 = fA1 & 3;
    const int kB0 = fA0 >> 5, nB0 = (fA0 & 31) * 4;
    const int kB1 = fA1 >> 5, nB1 = (fA1 & 31) * 4;
    const int rowA0 = bm + mA0, rowA1 = bm + mA1;

    float c[2][8][4];
#pragma unroll
    for (int mt = 0; mt < 2; mt++)
#pragma unroll
        for (int nt = 0; nt < 8; nt++)
#pragma unroll
            for (int q = 0; q < 4; q++) c[mt][nt][q] = 0.f;

    float4 ra0, ra1, rb0, rb1;

#define LOAD_REGS(K0)                                                              \
    {                                                                              \
        ra0 = make_float4(0.f, 0.f, 0.f, 0.f);                                     \
        ra1 = make_float4(0.f, 0.f, 0.f, 0.f);                                     \
        if (rowA0 < M) ra0 = *(const float4*)(X + (size_t)rowA0 * 128 + (K0) + kqA0 * 4); \
        if (rowA1 < M) ra1 = *(const float4*)(X + (size_t)rowA1 * 128 + (K0) + kqA1 * 4); \
        rb0 = *(const float4*)(W + (size_t)((K0) + kB0) * 128 + nB0);              \
        rb1 = *(const float4*)(W + (size_t)((K0) + kB1) * 128 + nB1);              \
    }

#define STORE_BUF(B)                                                               \
    {                                                                              \
        float4 u;                                                                  \
        u.x = tf32r(ra0.x); u.y = tf32r(ra0.y); u.z = tf32r(ra0.z); u.w = tf32r(ra0.w); \
        *(float4*)&Am[B][mA0][kqA0 * 4] = u;                                       \
        u.x = tf32r(ra1.x); u.y = tf32r(ra1.y); u.z = tf32r(ra1.z); u.w = tf32r(ra1.w); \
        *(float4*)&Am[B][mA1][kqA1 * 4] = u;                                       \
        u.x = tf32r(rb0.x); u.y = tf32r(rb0.y); u.z = tf32r(rb0.z); u.w = tf32r(rb0.w); \
        *(float4*)&Bs[B][kB0][nB0] = u;                                            \
        u.x = tf32r(rb1.x); u.y = tf32r(rb1.y); u.z = tf32r(rb1.z); u.w = tf32r(rb1.w); \
        *(float4*)&Bs[B][kB1][nB1] = u;                                            \
    }

    LOAD_REGS(0);
    STORE_BUF(0);
    __syncthreads();

    int cur = 0;
#pragma unroll
    for (int it = 0; it < 8; it++) {
        if (it < 7) LOAD_REGS((it + 1) * 16);
#pragma unroll
        for (int kk = 0; kk < 16; kk += 8) {
            uint32_t a[2][4], b[8][2];
#pragma unroll
            for (int mt = 0; mt < 2; mt++) {
                int r = warp_m * 32 + mt * 16 + g;
                a[mt][0] = __float_as_uint(Am[cur][r][kk + t]);
                a[mt][1] = __float_as_uint(Am[cur][r + 8][kk + t]);
                a[mt][2] = __float_as_uint(Am[cur][r][kk + t + 4]);
                a[mt][3] = __float_as_uint(Am[cur][r + 8][kk + t + 4]);
            }
#pragma unroll
            for (int nt = 0; nt < 8; nt++) {
                int cn = warp_n * 64 + nt * 8 + g;
                b[nt][0] = __float_as_uint(Bs[cur][kk + t][cn]);
                b[nt][1] = __float_as_uint(Bs[cur][kk + t + 4][cn]);
            }
#pragma unroll
            for (int mt = 0; mt < 2; mt++)
#pragma unroll
                for (int nt = 0; nt < 8; nt++) {
                    asm volatile(
                        "mma.sync.aligned.m16n8k8.row.col.f32.tf32.tf32.f32 "
                        "{%0,%1,%2,%3},{%4,%5,%6,%7},{%8,%9},{%0,%1,%2,%3};"
                        : "+f"(c[mt][nt][0]), "+f"(c[mt][nt][1]),
                          "+f"(c[mt][nt][2]), "+f"(c[mt][nt][3])
                        : "r"(a[mt][0]), "r"(a[mt][1]), "r"(a[mt][2]), "r"(a[mt][3]),
                          "r"(b[nt][0]), "r"(b[nt][1]));
                }
        }
        if (it < 7) {
            STORE_BUF(cur ^ 1);
            __syncthreads();
            cur ^= 1;
        }
    }
#undef LOAD_REGS
#undef STORE_BUF

    // epilogue: +bias, convert to fp16, store half2 pairs
#pragma unroll
    for (int nt = 0; nt < 8; nt++) {
        int col = warp_n * 64 + nt * 8 + t * 2;
        float2 bb = *(const float2*)(bias + col);
#pragma unroll
        for (int mt = 0; mt < 2; mt++) {
            int r0 = bm + warp_m * 32 + mt * 16 + g;
            if (r0 < M) {
                __half2 h = __floats2half2_rn(c[mt][nt][0] + bb.x, c[mt][nt][1] + bb.y);
                *(__half2*)(Y + (size_t)r0 * 128 + col) = h;
            }
            int r1 = r0 + 8;
            if (r1 < M) {
                __half2 h = __floats2half2_rn(c[mt][nt][2] + bb.x, c[mt][nt][3] + bb.y);
                *(__half2*)(Y + (size_t)r1 * 128 + col) = h;
            }
        }
    }
}

// ---------------- CSR gather-reduce, fp16 table -> fp32 acc -----------------
__global__ void reduce128(int which) {
    const __half* Wh = (which == 0) ? g_Wh_uu : (which == 1) ? g_Wh_iu : g_Wh_ui;
    float4* acc = (which == 0) ? g_acc_uu : (which == 1) ? g_acc_iu : g_acc_ui;
    int w = (blockIdx.x * blockDim.x + threadIdx.x) >> 5;
    int lane = threadIdx.x & 31;
    if (w >= 100000) return;
    int off = which * 100000;
    int beg = g_rowstart[off + w];
    int end = beg + g_deg[off + w];
    float4 s = make_float4(0.f, 0.f, 0.f, 0.f);
    for (int j = beg; j < end; j++) {
        int sc = g_slot[j];
        uint2 u = __ldg((const uint2*)(Wh + (size_t)sc * 128 + lane * 4));
        float2 f0 = __half22float2(*(__half2*)&u.x);
        float2 f1 = __half22float2(*(__half2*)&u.y);
        s.x += f0.x; s.y += f0.y; s.z += f1.x; s.w += f1.y;
    }
    __stcs(&acc[(size_t)w * 32 + lane], s);  // evict-first: keep Wh tables hot
}

// ---------------- skinny GEMM (both ntypes, one launch; mean+relu fused) ----
__global__ __launch_bounds__(256) void gemm16_both(
    const float* __restrict__ Wu, const float* __restrict__ bu,
    const float* __restrict__ Wi, const float* __restrict__ bi) {
    const bool item = blockIdx.x >= 1563;
    const float* W = item ? Wi : Wu;
    const float* b = item ? bi : bu;
    float* Y = item ? (float*)g_Wh1_iu : (float*)g_Wh1_uu;
    const int M = item ? NITEM : NUSER;
    const int base = (item ? blockIdx.x - 1563 : blockIdx.x) * 64;

    __shared__ float Xs[64][130];
    __shared__ float Ws[128 * 16];
    __shared__ float bs[16];
    int tid = threadIdx.x;
#pragma unroll
    for (int i = 0; i < 8; i++) Ws[tid + i * 256] = W[tid + i * 256];
    if (tid < 16) bs[tid] = b[tid];
#pragma unroll
    for (int i = 0; i < 8; i++) {
        int f = tid + i * 256;
        int r = f >> 5, c4 = f & 31;
        int row = base + r;
        float4 v = make_float4(0.f, 0.f, 0.f, 0.f);
        if (row < M) {
            if (!item) {
                float iu = 1.f / fmaxf((float)g_deg[row], 1.f);
                float ii = 1.f / fmaxf((float)g_deg[100000 + row], 1.f);
                float4 a = g_acc_uu[(size_t)row * 32 + c4];
                float4 c = g_acc_iu[(size_t)row * 32 + c4];
                v.x = fmaxf(a.x * iu + c.x * ii, 0.f);
                v.y = fmaxf(a.y * iu + c.y * ii, 0.f);
                v.z = fmaxf(a.z * iu + c.z * ii, 0.f);
                v.w = fmaxf(a.w * iu + c.w * ii, 0.f);
            } else {
                float inv = 1.f / fmaxf((float)g_deg[200000 + row], 1.f);
                float4 a = g_acc_ui[(size_t)row * 32 + c4];
                v.x = fmaxf(a.x * inv, 0.f);
                v.y = fmaxf(a.y * inv, 0.f);
                v.z = fmaxf(a.z * inv, 0.f);
                v.w = fmaxf(a.w * inv, 0.f);
            }
        }
        Xs[r][c4 * 4 + 0] = v.x; Xs[r][c4 * 4 + 1] = v.y;
        Xs[r][c4 * 4 + 2] = v.z; Xs[r][c4 * 4 + 3] = v.w;
    }
    __syncthreads();
    int r = tid >> 2, cb = (tid & 3) * 4;
    float4 acc = make_float4(0.f, 0.f, 0.f, 0.f);
#pragma unroll 8
    for (int k = 0; k < 128; k++) {
        float x = Xs[r][k];
        float4 w = *(float4*)&Ws[k * 16 + cb];
        acc.x = fmaf(x, w.x, acc.x);
        acc.y = fmaf(x, w.y, acc.y);
        acc.z = fmaf(x, w.z, acc.z);
        acc.w = fmaf(x, w.w, acc.w);
    }
    int row = base + r;
    if (row < M) {
        float4 o;
        o.x = acc.x + bs[cb + 0];
        o.y = acc.y + bs[cb + 1];
        o.z = acc.z + bs[cb + 2];
        o.w = acc.w + bs[cb + 3];
        *(float4*)(Y + (size_t)row * 16 + cb) = o;
    }
}

// ---------------- layer-1 reduce (both etypes) + mean combine -> d_out ------
__global__ void reduce16_final(float4* __restrict__ out) {
    int id = blockIdx.x * blockDim.x + threadIdx.x;
    int n = id >> 2, part = id & 3;
    if (n >= NUSER) return;
    float4 s0 = make_float4(0.f, 0.f, 0.f, 0.f);
    {
        int beg = g_rowstart[n], end = beg + g_deg[n];
        for (int j = beg; j < end; j++) {
            int sc = g_slot[j];
            float4 v = __ldg(&g_Wh1_uu[(size_t)sc * 4 + part]);
            s0.x += v.x; s0.y += v.y; s0.z += v.z; s0.w += v.w;
        }
    }
    float4 s1 = make_float4(0.f, 0.f, 0.f, 0.f);
    {
        int beg = g_rowstart[100000 + n], end = beg + g_deg[100000 + n];
        for (int j = beg; j < end; j++) {
            int sc = g_slot[j];
            float4 v = __ldg(&g_Wh1_iu[(size_t)sc * 4 + part]);
            s1.x += v.x; s1.y += v.y; s1.z += v.z; s1.w += v.w;
        }
    }
    float iu = 1.f / fmaxf((float)g_deg[n], 1.f);
    float ii = 1.f / fmaxf((float)g_deg[100000 + n], 1.f);
    float4 o;
    o.x = s0.x * iu + s1.x * ii;
    o.y = s0.y * iu + s1.y * ii;
    o.z = s0.z * iu + s1.z * ii;
    o.w = s0.w * iu + s1.w * ii;
    out[(size_t)n * 4 + part] = o;
}

// ---------------- launch ----------------
extern "C" void kernel_launch(void* const* d_in, const int* in_sizes, int n_in,
                              void* d_out, int out_size) {
    const float* embed_user = (const float*)d_in[0];
    const float* embed_item = (const float*)d_in[1];
    const int* src_uu = (const int*)d_in[2];
    const int* dst_uu = (const int*)d_in[3];
    const int* src_ui = (const int*)d_in[4];
    const int* dst_ui = (const int*)d_in[5];
    const int* src_iu = (const int*)d_in[6];
    const int* dst_iu = (const int*)d_in[7];
    const float* W0_uu = (const float*)d_in[8];
    const float* b0_uu = (const float*)d_in[9];
    const float* W0_ui = (const float*)d_in[10];
    const float* b0_ui = (const float*)d_in[11];
    const float* W0_iu = (const float*)d_in[12];
    const float* b0_iu = (const float*)d_in[13];
    const float* W1_uu = (const float*)d_in[14];
    const float* b1_uu = (const float*)d_in[15];
    const float* W1_iu = (const float*)d_in[18];
    const float* b1_iu = (const float*)d_in[19];

    const int e3blk = (3 * NE + 255) / 256;
    const int rblk = (100000 * 32 + 255) / 256;

    // ---- CSR build (4 launches) ----
    zero_deg<<<(NTOT + 255) / 256, 256>>>();
    hist_all<<<e3blk, 256>>>(dst_uu, dst_iu, dst_ui);
    offsets_k<<<(NTOT + 255) / 256, 256>>>();
    fill_all<<<e3blk, 256>>>(src_uu, dst_uu, src_iu, dst_iu, src_ui, dst_ui);

    // ---- layer 0: both user-sourced gemms back-to-back (embed_user L2 reuse),
    //      then their reduces from L2-resident fp16 Wh; item etype last.
    gemm128<<<(NUSER + 127) / 128, 256>>>(embed_user, W0_uu, b0_uu, NUSER, 0);
    gemm128<<<(NUSER + 127) / 128, 256>>>(embed_user, W0_ui, b0_ui, NUSER, 1);
    reduce128<<<rblk, 256>>>(0);   // uu: gather g_Wh_uu
    reduce128<<<rblk, 256>>>(2);   // ui: gather g_Wh_ui
    gemm128<<<(NITEM + 127) / 128, 256>>>(embed_item, W0_iu, b0_iu, NITEM, 2);
    reduce128<<<rblk, 256>>>(1);   // iu: gather g_Wh_iu

    // ---- layer 1: skinny GEMM (both ntypes), reduce + combine -> out ----
    gemm16_both<<<2 * 1563, 256>>>(W1_uu, b1_uu, W1_iu, b1_iu);
    reduce16_final<<<(NUSER * 4 + 255) / 256, 256>>>((float4*)d_out);
}